// round 1
// baseline (speedup 1.0000x reference)
#include <cuda_runtime.h>
#include <stdint.h>

#define Bn 4096
#define Dn 16
#define Mn 4
#define Rn 2048
#define Cn 10
#define BT 32
#define WARPS 8
#define THREADS (WARPS * 32)
#define RPW (Rn / WARPS)   // 256 rules per warp
#define EPSV 1e-9f

// scratch (module-load allocation, allowed)
__device__ uint32_t g_packed[Rn];
__device__ float    g_cs[Rn * 12];   // padded to 12 (3 x float4)

// ---------------------------------------------------------------------------
// prep: pack rule indices (2 bits x 16 dims -> u32) and fold consequents over j
// ---------------------------------------------------------------------------
__global__ void anfis_prep(const float* __restrict__ cons,
                           const int*   __restrict__ rules) {
    int r = blockIdx.x * blockDim.x + threadIdx.x;
    if (r >= Rn) return;
    uint32_t p = 0;
#pragma unroll
    for (int d = 0; d < Dn; d++)
        p |= ((uint32_t)rules[r * Dn + d] & 3u) << (2 * d);
    g_packed[r] = p;

    float s[Cn];
#pragma unroll
    for (int c = 0; c < Cn; c++) s[c] = 0.f;
    const float* base = cons + (size_t)r * (Dn + 1) * Cn;
#pragma unroll
    for (int j = 0; j <= Dn; j++)
#pragma unroll
        for (int c = 0; c < Cn; c++) s[c] += base[j * Cn + c];
#pragma unroll
    for (int c = 0; c < Cn; c++) g_cs[r * 12 + c] = s[c];
    g_cs[r * 12 + 10] = 0.f;
    g_cs[r * 12 + 11] = 0.f;
}

// ---------------------------------------------------------------------------
// main: one CTA = 32 batch rows x all 2048 rules
// ---------------------------------------------------------------------------
// smem layout (floats):
//   tbl   [4][256][32]   32768
//   mf    [64][32]        2048
//   xs    [32][16]         512
//   stage [W][32][33]     8448
//   wsum  [W][32]          256
//   wacc  [W][10][32]     2560
//   inv   [32]              32
//   sx    [32]              32
#define SMEM_FLOATS (32768 + 2048 + 512 + WARPS*32*33 + WARPS*32 + WARPS*10*32 + 32 + 32)
#define SMEM_BYTES  (SMEM_FLOATS * 4)

__global__ void __launch_bounds__(THREADS, 1)
anfis_main(const float* __restrict__ x,
           const float* __restrict__ centers,
           const float* __restrict__ widths,
           float* __restrict__ out,     // (B, C)
           float* __restrict__ nf,      // (B, R)
           float* __restrict__ xext,    // (B, D+1)
           int write_aux) {
    extern __shared__ float sm[];
    float* tbl   = sm;                          // 4*256*32
    float* mf    = tbl   + 4 * 256 * 32;        // 64*32
    float* xs    = mf    + 64 * 32;             // 32*16
    float* stage = xs    + 32 * 16;             // W*32*33
    float* wsum  = stage + WARPS * 32 * 33;     // W*32
    float* wacc  = wsum  + WARPS * 32;          // W*10*32
    float* inv_s = wacc  + WARPS * 10 * 32;     // 32
    float* sx    = inv_s + 32;                  // 32

    const int tid  = threadIdx.x;
    const int w    = tid >> 5;
    const int lane = tid & 31;
    const int b0   = blockIdx.x * BT;

    // load x tile (coalesced)
    for (int i = tid; i < BT * Dn; i += THREADS)
        xs[i] = x[(size_t)b0 * Dn + i];
    __syncthreads();

    // row sums of x_ext
    if (tid < BT) {
        float s = 1.f;
#pragma unroll
        for (int d = 0; d < Dn; d++) s += xs[tid * Dn + d];
        sx[tid] = s;
    }

    // membership values: mf[dm][b] = exp(-(x-c)^2 / (2 w^2))
    for (int e = tid; e < 64 * 32; e += THREADS) {
        int dm = e >> 5, b = e & 31;
        int d = dm >> 2, m = dm & 3;
        float cc = centers[d * Mn + m];
        float ww = widths[d * Mn + m];
        float df = xs[b * Dn + d] - cc;
        mf[dm * 32 + b] = expf(-df * df / (2.f * ww * ww));
    }
    __syncthreads();

    // group tables: tbl[g][idx][b] = prod of 4 memberships (lane = b, conflict-free)
    for (int pp = w; pp < 4 * 256; pp += WARPS) {
        int g = pp >> 8, idx = pp & 255;
        float f = mf[((g * 4 + 0) * 4 + ( idx        & 3)) * 32 + lane]
                * mf[((g * 4 + 1) * 4 + ((idx >> 2)  & 3)) * 32 + lane]
                * mf[((g * 4 + 2) * 4 + ((idx >> 4)  & 3)) * 32 + lane]
                * mf[((g * 4 + 3) * 4 + ((idx >> 6)  & 3)) * 32 + lane];
        tbl[pp * 32 + lane] = f;
    }
    __syncthreads();

    // main loop: lane = batch, warp-uniform rule index
    const float4* cs4 = (const float4*)g_cs;
    float acc[Cn];
#pragma unroll
    for (int c = 0; c < Cn; c++) acc[c] = 0.f;
    float fsum = 0.f;

    const int rbase = w * RPW;
    float* stg = stage + w * 32 * 33;

    for (int ch = 0; ch < RPW / 32; ch++) {
        const int r0 = rbase + ch * 32;
#pragma unroll 4
        for (int rl = 0; rl < 32; rl++) {
            const int r = r0 + rl;
            const uint32_t pk = g_packed[r];
            float f = tbl[(        ( pk         & 255u)) * 32 + lane];
            f      *= tbl[(256u  + ((pk >>  8)  & 255u)) * 32 + lane];
            f      *= tbl[(512u  + ((pk >> 16)  & 255u)) * 32 + lane];
            f      *= tbl[(768u  +  (pk >> 24)         ) * 32 + lane];
            stg[rl * 33 + lane] = f;
            fsum += f;
            float4 A = cs4[r * 3 + 0];
            float4 Bv = cs4[r * 3 + 1];
            float4 Cv = cs4[r * 3 + 2];
            acc[0] += f * A.x;  acc[1] += f * A.y;
            acc[2] += f * A.z;  acc[3] += f * A.w;
            acc[4] += f * Bv.x; acc[5] += f * Bv.y;
            acc[6] += f * Bv.z; acc[7] += f * Bv.w;
            acc[8] += f * Cv.x; acc[9] += f * Cv.y;
        }
        __syncwarp();
        if (write_aux) {
            // transposed, coalesced store of raw fs
#pragma unroll 8
            for (int rr = 0; rr < 32; rr++)
                nf[(size_t)(b0 + rr) * Rn + r0 + lane] = stg[lane * 33 + rr];
        }
        __syncwarp();
    }

    // cross-warp reduction buffers
    wsum[w * 32 + lane] = fsum;
#pragma unroll
    for (int c = 0; c < Cn; c++)
        wacc[(w * Cn + c) * 32 + lane] = acc[c];
    __syncthreads();

    if (tid < BT) {
        float s = 0.f;
#pragma unroll
        for (int ww = 0; ww < WARPS; ww++) s += wsum[ww * 32 + tid];
        inv_s[tid] = 1.f / (s + EPSV);
    }
    __syncthreads();

    // out[b][c] = sx[b] * inv[b] * sum_r fs * Cs
    for (int i = tid; i < BT * Cn; i += THREADS) {
        int c = i >> 5, b = i & 31;
        float a = 0.f;
#pragma unroll
        for (int ww = 0; ww < WARPS; ww++) a += wacc[(ww * Cn + c) * 32 + b];
        out[(size_t)(b0 + b) * Cn + c] = sx[b] * inv_s[b] * a;
    }

    if (write_aux) {
        // x_ext output
        for (int i = tid; i < BT * (Dn + 1); i += THREADS) {
            int b = i / (Dn + 1), j = i % (Dn + 1);
            xext[(size_t)(b0 + b) * (Dn + 1) + j] = (j < Dn) ? xs[b * Dn + j] : 1.f;
        }
        // normalize pass: scale this CTA's raw fs region (L2 resident)
        __threadfence();
        __syncthreads();
        const size_t base = (size_t)b0 * Rn;
        for (int i = tid; i < BT * Rn; i += THREADS)
            nf[base + i] *= inv_s[i >> 11];   // R = 2048 = 1<<11
    }
}

// ---------------------------------------------------------------------------
extern "C" void kernel_launch(void* const* d_in, const int* in_sizes, int n_in,
                              void* d_out, int out_size) {
    const float* x       = (const float*)d_in[0];
    const float* centers = (const float*)d_in[1];
    const float* widths  = (const float*)d_in[2];
    const float* cons    = (const float*)d_in[3];
    const int*   rules   = (const int*)d_in[4];

    float* out = (float*)d_out;
    const long total = (long)Bn * Cn + (long)Bn * Rn + (long)Bn * (Dn + 1);
    const int write_aux = (out_size >= total) ? 1 : 0;
    float* nf   = out + (size_t)Bn * Cn;
    float* xext = nf + (size_t)Bn * Rn;

    anfis_prep<<<(Rn + 255) / 256, 256>>>(cons, rules);

    cudaFuncSetAttribute(anfis_main, cudaFuncAttributeMaxDynamicSharedMemorySize,
                         SMEM_BYTES);
    anfis_main<<<Bn / BT, THREADS, SMEM_BYTES>>>(x, centers, widths,
                                                 out, nf, xext, write_aux);
}

// round 2
// speedup vs baseline: 1.2978x; 1.2978x over previous
#include <cuda_runtime.h>
#include <stdint.h>

#define Bn 4096
#define Dn 16
#define Mn 4
#define Rn 2048
#define Cn 10
#define BT 32
#define WARPS 16
#define THREADS (WARPS * 32)
#define RPW (Rn / WARPS)   // 128 rules per warp
#define EPSV 1e-9f

// table layout: groups of dims {0-3},{4-7},{8-11} -> 256 entries each,
// groups {12,13},{14,15} -> 16 entries each. total 800 entries x 32 lanes.
#define TBL_ENTRIES 800

// scratch (module-load allocation, allowed)
__device__ uint32_t g_packed[Rn];
__device__ float    g_cs[Rn * 12];   // padded to 12 (3 x float4)

// ---------------------------------------------------------------------------
// prep: pack rule indices (2 bits x 16 dims -> u32) and fold consequents over j
// ---------------------------------------------------------------------------
__global__ void anfis_prep(const float* __restrict__ cons,
                           const int*   __restrict__ rules) {
    int r = blockIdx.x * blockDim.x + threadIdx.x;
    if (r >= Rn) return;
    uint32_t p = 0;
#pragma unroll
    for (int d = 0; d < Dn; d++)
        p |= ((uint32_t)rules[r * Dn + d] & 3u) << (2 * d);
    g_packed[r] = p;

    float s[Cn];
#pragma unroll
    for (int c = 0; c < Cn; c++) s[c] = 0.f;
    const float* base = cons + (size_t)r * (Dn + 1) * Cn;
#pragma unroll
    for (int j = 0; j <= Dn; j++)
#pragma unroll
        for (int c = 0; c < Cn; c++) s[c] += base[j * Cn + c];
#pragma unroll
    for (int c = 0; c < Cn; c++) g_cs[r * 12 + c] = s[c];
    g_cs[r * 12 + 10] = 0.f;
    g_cs[r * 12 + 11] = 0.f;
}

// ---------------------------------------------------------------------------
// main: one CTA = 32 batch rows x all 2048 rules, 16 warps
// ---------------------------------------------------------------------------
// smem layout (floats):
//   tbl   [800][32]      25600
//   mf    [64][32]        2048
//   xs    [32][16]         512
//   stage [W][32][33]    16896
//   wsum  [W][32]          512
//   wacc  [W][10][32]     5120
//   inv   [32]              32
//   sx    [32]              32
#define SMEM_FLOATS (TBL_ENTRIES*32 + 2048 + 512 + WARPS*32*33 + WARPS*32 + WARPS*10*32 + 32 + 32)
#define SMEM_BYTES  (SMEM_FLOATS * 4)

__global__ void __launch_bounds__(THREADS, 1)
anfis_main(const float* __restrict__ x,
           const float* __restrict__ centers,
           const float* __restrict__ widths,
           float* __restrict__ out,     // (B, C)
           float* __restrict__ nf,      // (B, R)
           float* __restrict__ xext,    // (B, D+1)
           int write_aux) {
    extern __shared__ float sm[];
    float* tbl   = sm;                          // 800*32
    float* mf    = tbl   + TBL_ENTRIES * 32;    // 64*32
    float* xs    = mf    + 64 * 32;             // 32*16
    float* stage = xs    + 32 * 16;             // W*32*33
    float* wsum  = stage + WARPS * 32 * 33;     // W*32
    float* wacc  = wsum  + WARPS * 32;          // W*10*32
    float* inv_s = wacc  + WARPS * 10 * 32;     // 32
    float* sx    = inv_s + 32;                  // 32

    const int tid  = threadIdx.x;
    const int w    = tid >> 5;
    const int lane = tid & 31;
    const int b0   = blockIdx.x * BT;

    // load x tile (coalesced)
    for (int i = tid; i < BT * Dn; i += THREADS)
        xs[i] = x[(size_t)b0 * Dn + i];
    __syncthreads();

    // row sums of x_ext
    if (tid < BT) {
        float s = 1.f;
#pragma unroll
        for (int d = 0; d < Dn; d++) s += xs[tid * Dn + d];
        sx[tid] = s;
    }

    // membership values: mf[dm][b] = exp(-(x-c)^2 / (2 w^2))
    for (int e = tid; e < 64 * 32; e += THREADS) {
        int dm = e >> 5, b = e & 31;
        int d = dm >> 2, m = dm & 3;
        float cc = centers[d * Mn + m];
        float ww = widths[d * Mn + m];
        float df = xs[b * Dn + d] - cc;
        mf[dm * 32 + b] = expf(-df * df / (2.f * ww * ww));
    }
    __syncthreads();

    // group-product tables (lane = batch, conflict-free)
    // pp in [0,256): g0 dims 0-3; [256,512): g1 dims 4-7; [512,768): g2 dims 8-11
    // pp in [768,784): g3 dims 12-13; [784,800): g4 dims 14-15
    for (int pp = w; pp < TBL_ENTRIES; pp += WARPS) {
        float f;
        if (pp < 768) {
            int g = pp >> 8, idx = pp & 255;
            f = mf[((g * 4 + 0) * 4 + ( idx        & 3)) * 32 + lane]
              * mf[((g * 4 + 1) * 4 + ((idx >> 2)  & 3)) * 32 + lane]
              * mf[((g * 4 + 2) * 4 + ((idx >> 4)  & 3)) * 32 + lane]
              * mf[((g * 4 + 3) * 4 + ((idx >> 6)  & 3)) * 32 + lane];
        } else if (pp < 784) {
            int idx = pp - 768;
            f = mf[(12 * 4 + ( idx       & 3)) * 32 + lane]
              * mf[(13 * 4 + ((idx >> 2) & 3)) * 32 + lane];
        } else {
            int idx = pp - 784;
            f = mf[(14 * 4 + ( idx       & 3)) * 32 + lane]
              * mf[(15 * 4 + ((idx >> 2) & 3)) * 32 + lane];
        }
        tbl[pp * 32 + lane] = f;
    }
    __syncthreads();

    // main loop: lane = batch, warp-uniform rule index
    const float4* cs4 = (const float4*)g_cs;
    const float* tb = tbl + lane;
    float acc[Cn];
#pragma unroll
    for (int c = 0; c < Cn; c++) acc[c] = 0.f;
    float fsum = 0.f;

    const int rbase = w * RPW;
    float* stg = stage + w * 32 * 33;

    for (int ch = 0; ch < RPW / 32; ch++) {
        const int r0 = rbase + ch * 32;
#pragma unroll 4
        for (int rl = 0; rl < 32; rl++) {
            const int r = r0 + rl;
            const uint32_t pk = g_packed[r];
            float f0 = tb[(         ( pk         & 255u)) * 32];
            float f1 = tb[(256u   + ((pk >>  8)  & 255u)) * 32];
            float f2 = tb[(512u   + ((pk >> 16)  & 255u)) * 32];
            float f3 = tb[(768u   + ((pk >> 24)  &  15u)) * 32];
            float f4 = tb[(784u   +  (pk >> 28)         ) * 32];
            float f = ((f0 * f1) * (f2 * f3)) * f4;
            stg[rl * 33 + lane] = f;
            fsum += f;
            float4 A  = cs4[r * 3 + 0];
            float4 Bv = cs4[r * 3 + 1];
            float4 Cv = cs4[r * 3 + 2];
            acc[0] += f * A.x;  acc[1] += f * A.y;
            acc[2] += f * A.z;  acc[3] += f * A.w;
            acc[4] += f * Bv.x; acc[5] += f * Bv.y;
            acc[6] += f * Bv.z; acc[7] += f * Bv.w;
            acc[8] += f * Cv.x; acc[9] += f * Cv.y;
        }
        __syncwarp();
        if (write_aux) {
            // transposed, coalesced store of raw fs
#pragma unroll 8
            for (int rr = 0; rr < 32; rr++)
                nf[(size_t)(b0 + rr) * Rn + r0 + lane] = stg[lane * 33 + rr];
        }
        __syncwarp();
    }

    // cross-warp reduction buffers
    wsum[w * 32 + lane] = fsum;
#pragma unroll
    for (int c = 0; c < Cn; c++)
        wacc[(w * Cn + c) * 32 + lane] = acc[c];
    __syncthreads();

    if (tid < BT) {
        float s = 0.f;
#pragma unroll
        for (int ww = 0; ww < WARPS; ww++) s += wsum[ww * 32 + tid];
        inv_s[tid] = 1.f / (s + EPSV);
    }
    __syncthreads();

    // out[b][c] = sx[b] * inv[b] * sum_r fs * Cs
    for (int i = tid; i < BT * Cn; i += THREADS) {
        int c = i >> 5, b = i & 31;
        float a = 0.f;
#pragma unroll
        for (int ww = 0; ww < WARPS; ww++) a += wacc[(ww * Cn + c) * 32 + b];
        out[(size_t)(b0 + b) * Cn + c] = sx[b] * inv_s[b] * a;
    }

    if (write_aux) {
        // x_ext output
        for (int i = tid; i < BT * (Dn + 1); i += THREADS) {
            int b = i / (Dn + 1), j = i % (Dn + 1);
            xext[(size_t)(b0 + b) * (Dn + 1) + j] = (j < Dn) ? xs[b * Dn + j] : 1.f;
        }
        // normalize pass: scale this CTA's raw fs region (L2 resident)
        __threadfence();
        __syncthreads();
        const size_t base = (size_t)b0 * Rn;
        for (int i = tid; i < BT * Rn; i += THREADS)
            nf[base + i] *= inv_s[i >> 11];   // R = 2048 = 1<<11
    }
}

// ---------------------------------------------------------------------------
extern "C" void kernel_launch(void* const* d_in, const int* in_sizes, int n_in,
                              void* d_out, int out_size) {
    const float* x       = (const float*)d_in[0];
    const float* centers = (const float*)d_in[1];
    const float* widths  = (const float*)d_in[2];
    const float* cons    = (const float*)d_in[3];
    const int*   rules   = (const int*)d_in[4];

    float* out = (float*)d_out;
    const long total = (long)Bn * Cn + (long)Bn * Rn + (long)Bn * (Dn + 1);
    const int write_aux = (out_size >= total) ? 1 : 0;
    float* nf   = out + (size_t)Bn * Cn;
    float* xext = nf + (size_t)Bn * Rn;

    anfis_prep<<<(Rn + 255) / 256, 256>>>(cons, rules);

    cudaFuncSetAttribute(anfis_main, cudaFuncAttributeMaxDynamicSharedMemorySize,
                         SMEM_BYTES);
    anfis_main<<<Bn / BT, THREADS, SMEM_BYTES>>>(x, centers, widths,
                                                 out, nf, xext, write_aux);
}